// round 12
// baseline (speedup 1.0000x reference)
#include <cuda_runtime.h>
#include <math.h>

#define NBOARD 13
#define SN 169
#define NG 2048
#define NT 192
#define GRID 148
#define EPSV 1e-5f
#define LSMIN -5.0f
#define LSMAX 2.0f

#define HSF 78            // h row stride (floats): FEAT [0,36), AGG [40,76)
#define HSU 39            // in ull (odd -> conflict-free 8B accesses)
#define AOFF 40
#define AOFFU 20
#define OSF 38            // out row stride (19 ull, odd)
#define GB (SN * HSF)
#define GBU (SN * HSU)
#define OB (SN * OSF)

typedef unsigned long long ull;

__device__ __forceinline__ ull pk2(float x, float y) {
    ull r; asm("mov.b64 %0, {%1,%2};" : "=l"(r) : "f"(x), "f"(y)); return r;
}
__device__ __forceinline__ float2 upk2(ull a) {
    float2 v; asm("mov.b64 {%0,%1}, %2;" : "=f"(v.x), "=f"(v.y) : "l"(a)); return v;
}
__device__ __forceinline__ ull ffma2(ull a, ull b, ull c) {
    ull d; asm("fma.rn.f32x2 %0, %1, %2, %3;" : "=l"(d) : "l"(a), "l"(b), "l"(c)); return d;
}
__device__ __forceinline__ ull fadd2(ull a, ull b) {
    ull d; asm("add.rn.f32x2 %0, %1, %2;" : "=l"(d) : "l"(a), "l"(b)); return d;
}
__device__ __forceinline__ ull fmul2(ull a, ull b) {
    ull d; asm("mul.rn.f32x2 %0, %1, %2;" : "=l"(d) : "l"(a), "l"(b)); return d;
}

__device__ float g_pooled[NG * 72];

struct __align__(16) Smem {
    float wc3[36 * 72];
    float wr2[36 * 72];
    float wc2[18 * 36];
    float wr1[18 * 36];
    float E1[56];             // emb @ wc1
    float embs[56];
    float bc1[18], bc2[36], bc3[72];
    float br1[36], br2[72];
    float g1v[18], be1v[18], a1v[18];
    float g2v[36], be2v[36], a2v[36];
    float g3v[72], be3v[72], a3v[72];
    float redP[192], redQ[192];
    float redS[144], redC[144];
    float dis[170];
    float h[2 * SN * HSF];
    float out[2 * SN * OSF];
};

__device__ __forceinline__ void cp_sm(float* dst, const float* src, int n, int t) {
    for (int i = t; i < n; i += NT) dst[i] = src[i];
}

// packed gather: WU ull features from own row + 6 neighbors (conflict-free)
template<int WU>
__device__ __forceinline__ void gatherU(const ull* base, const ull* own, ull* dst,
                                        const int* nbU, const ull* dnb2, ull dd) {
    #pragma unroll 2
    for (int k = 0; k < WU; k++) {
        ull a = fmul2(own[k], dd);
        #pragma unroll
        for (int j = 0; j < 6; j++) a = ffma2(dnb2[j], base[nbU[j] + k], a);
        dst[k] = fmul2(a, dd);
    }
}

// acc[0:18) += inA @ W ; acc[18:36) += inB @ W (36-wide output slice), W in smem
template<int K, int RS>
__device__ __forceinline__ void mm2(const float* W0, const float* inA, const float* inB, ull* acc) {
    #pragma unroll 2
    for (int k = 0; k < K; k++) {
        const float aA = inA[k], aB = inB[k];
        const ull qA = pk2(aA, aA), qB = pk2(aB, aB);
        const ulonglong2* w = (const ulonglong2*)(W0 + k * RS);
        #pragma unroll
        for (int jv = 0; jv < 9; jv++) {
            ulonglong2 ww = w[jv];
            acc[2 * jv]      = ffma2(qA, ww.x, acc[2 * jv]);
            acc[2 * jv + 1]  = ffma2(qA, ww.y, acc[2 * jv + 1]);
            acc[18 + 2 * jv]     = ffma2(qB, ww.x, acc[18 + 2 * jv]);
            acc[18 + 2 * jv + 1] = ffma2(qB, ww.y, acc[18 + 2 * jv + 1]);
        }
    }
}

__device__ __forceinline__ void statpair(Smem& sm, int t, int Wf, int NS) {
    if (t < Wf * NS) {
        const int f = t % Wf, sI = t / Wf;
        float s = 0.f, s2 = 0.f;
        const float* pp = sm.out + f;
        for (int n = sI; n < SN; n += NS) { float v = pp[n * OSF]; s += v; s2 = fmaf(v, v, s2); }
        sm.redP[t] = s; sm.redQ[t] = s2;
    } else if (t >= 96 && t < 96 + Wf * NS) {
        const int u = t - 96, f = u % Wf, sI = u / Wf;
        float s = 0.f, s2 = 0.f;
        const float* pp = sm.out + OB + f;
        for (int n = sI; n < SN; n += NS) { float v = pp[n * OSF]; s += v; s2 = fmaf(v, v, s2); }
        sm.redP[t] = s; sm.redQ[t] = s2;
    }
}

__device__ __forceinline__ void scpair(Smem& sm, int t, int Wf, int NS,
                                       const float* gv, const float* bev, const float* av, int poff) {
    const float invS = 1.0f / (float)SN;
    if (t < Wf) {
        float s = 0.f, s2 = 0.f;
        for (int i = 0; i < NS; i++) { s += sm.redP[t + i * Wf]; s2 += sm.redQ[t + i * Wf]; }
        float m = s * invS, af = av[poff + t];
        float var = s2 * invS - m * m * af * (2.0f - af);
        float S = gv[poff + t] * rsqrtf(var + EPSV);
        sm.redS[t] = S; sm.redC[t] = bev[poff + t] - af * m * S;
    } else if (t >= 96 && t < 96 + Wf) {
        const int f = t - 96;
        float s = 0.f, s2 = 0.f;
        for (int i = 0; i < NS; i++) { s += sm.redP[96 + f + i * Wf]; s2 += sm.redQ[96 + f + i * Wf]; }
        float m = s * invS, af = av[poff + f];
        float var = s2 * invS - m * m * af * (2.0f - af);
        float S = gv[poff + f] * rsqrtf(var + EPSV);
        sm.redS[36 + f] = S; sm.redC[36 + f] = bev[poff + f] - af * m * S;
    }
}

__global__ void __launch_bounds__(NT) gnn_kernel(
    const int* __restrict__ x,
    const float* __restrict__ emb,
    const float* __restrict__ wc1, const float* __restrict__ bc1,
    const float* __restrict__ wc2, const float* __restrict__ bc2,
    const float* __restrict__ wc3, const float* __restrict__ bc3,
    const float* __restrict__ wr1, const float* __restrict__ br1,
    const float* __restrict__ wr2, const float* __restrict__ br2,
    const float* __restrict__ g1, const float* __restrict__ be1, const float* __restrict__ a1,
    const float* __restrict__ g2, const float* __restrict__ be2, const float* __restrict__ a2,
    const float* __restrict__ g3, const float* __restrict__ be3, const float* __restrict__ a3)
{
    extern __shared__ char smraw[];
    Smem& sm = *reinterpret_cast<Smem*>(smraw);
    const int t = threadIdx.x;
    const bool isNode = (t < SN);
    ull* const hU = (ull*)sm.h;
    const float invS = 1.0f / (float)SN;

    cp_sm(sm.wc3, wc3, 36 * 72, t);
    cp_sm(sm.wr2, wr2, 36 * 72, t);
    cp_sm(sm.wc2, wc2, 18 * 36, t);
    cp_sm(sm.wr1, wr1, 18 * 36, t);
    cp_sm(sm.bc1, bc1, 18, t);  cp_sm(sm.bc2, bc2, 36, t);  cp_sm(sm.bc3, bc3, 72, t);
    cp_sm(sm.br1, br1, 36, t);  cp_sm(sm.br2, br2, 72, t);
    cp_sm(sm.g1v, g1, 18, t);   cp_sm(sm.be1v, be1, 18, t); cp_sm(sm.a1v, a1, 18, t);
    cp_sm(sm.g2v, g2, 36, t);   cp_sm(sm.be2v, be2, 36, t); cp_sm(sm.a2v, a2, 36, t);
    cp_sm(sm.g3v, g3, 72, t);   cp_sm(sm.be3v, be3, 72, t); cp_sm(sm.a3v, a3, 72, t);
    cp_sm(sm.embs, emb, 3 * 18, t);

    if (t < 54) {
        const int e = t / 18, j = t % 18;
        float s = 0.f;
        #pragma unroll
        for (int k = 0; k < 18; k++) s += emb[e * 18 + k] * wc1[k * 18 + j];
        sm.E1[e * 18 + j] = s;
    }

    int nbU[6], nbi[6];
    ull dnb2[6];
    float disn = 0.f;
    if (isNode) {
        const int r = t / NBOARD, c = t % NBOARD;
        const int drr[6] = { -1, 1, 0, 0, -1, 1 };
        const int dcc[6] = { 0, 0, -1, 1, 1, -1 };
        int deg = 1;
        #pragma unroll
        for (int j = 0; j < 6; j++) {
            int rr = r + drr[j], cc = c + dcc[j];
            if (rr >= 0 && rr < NBOARD && cc >= 0 && cc < NBOARD) { nbi[j] = rr * NBOARD + cc; deg++; }
            else nbi[j] = t;
            nbU[j] = nbi[j] * HSU;
        }
        disn = rsqrtf((float)deg);
        sm.dis[t] = disn;
    }
    __syncthreads();
    if (isNode) {
        #pragma unroll
        for (int j = 0; j < 6; j++) {
            const float d = (nbi[j] == t) ? 0.f : sm.dis[nbi[j]];
            dnb2[j] = pk2(d, d);
        }
    }
    __syncthreads();

    const ull dd = pk2(disn, disn);
    float* const hA = sm.h + t * HSF;
    float* const hB = sm.h + GB + t * HSF;
    ull* const haU = hU + t * HSU;
    ull* const hbU = hU + GBU + t * HSU;
    float* const oA = sm.out + t * OSF;
    float* const oB = sm.out + OB + t * OSF;

    for (int p = blockIdx.x; p < NG / 2; p += GRID) {
        const int gA = 2 * p, gB2 = 2 * p + 1;

        // ---- lookup ----
        ull h0A[9], h0B[9];
        if (isNode) {
            const int xa = x[gA * SN + t];
            const int xb = x[gB2 * SN + t];
            const ull* ea = (const ull*)&sm.embs[xa * 18];
            const ull* eb = (const ull*)&sm.embs[xb * 18];
            const ull* fa = (const ull*)&sm.E1[xa * 18];
            const ull* fb = (const ull*)&sm.E1[xb * 18];
            #pragma unroll
            for (int i = 0; i < 9; i++) { h0A[i] = ea[i]; h0B[i] = eb[i]; haU[i] = fa[i]; hbU[i] = fb[i]; }
        }
        __syncthreads();

        // ================= Layer 1: conv = gather(E1x) + bc1 ================
        if (isNode) {
            const ull* b1 = (const ull*)sm.bc1;
            ull aU[9];
            gatherU<9>(hU, haU, aU, nbU, dnb2, dd);
            ull* ouA = (ull*)oA;
            #pragma unroll
            for (int i = 0; i < 9; i++) ouA[i] = fadd2(aU[i], b1[i]);
            gatherU<9>(hU + GBU, hbU, aU, nbU, dnb2, dd);
            ull* ouB = (ull*)oB;
            #pragma unroll
            for (int i = 0; i < 9; i++) ouB[i] = fadd2(aU[i], b1[i]);
        }
        __syncthreads();
        statpair(sm, t, 18, 5);
        __syncthreads();
        scpair(sm, t, 18, 5, sm.g1v, sm.be1v, sm.a1v, 0);
        __syncthreads();
        if (isNode) {
            const ull* ouA = (const ull*)oA; const ull* ouB = (const ull*)oB;
            const ull* SuA = (const ull*)sm.redS;        const ull* CuA = (const ull*)sm.redC;
            const ull* SuB = (const ull*)&sm.redS[36];   const ull* CuB = (const ull*)&sm.redC[36];
            #pragma unroll
            for (int i = 0; i < 9; i++) {
                haU[i] = fadd2(ffma2(ouA[i], SuA[i], CuA[i]), h0A[i]);
                hbU[i] = fadd2(ffma2(ouB[i], SuB[i], CuB[i]), h0B[i]);
            }
        }
        __syncthreads();

        // ================= Layer 2 (18->36) =================================
        ull accR[36];
        if (isNode) {
            gatherU<9>(hU, haU, haU + AOFFU, nbU, dnb2, dd);
            gatherU<9>(hU + GBU, hbU, hbU + AOFFU, nbU, dnb2, dd);
            ull acc[36];
            const ull* b2 = (const ull*)sm.bc2;
            #pragma unroll
            for (int i = 0; i < 18; i++) { acc[i] = b2[i]; acc[18 + i] = b2[i]; }
            mm2<18, 36>(sm.wc2, hA + AOFF, hB + AOFF, acc);
            ull* ouA = (ull*)oA; ull* ouB = (ull*)oB;
            #pragma unroll
            for (int i = 0; i < 18; i++) { ouA[i] = acc[i]; ouB[i] = acc[18 + i]; }
            const ull* r1 = (const ull*)sm.br1;
            #pragma unroll
            for (int i = 0; i < 18; i++) { accR[i] = r1[i]; accR[18 + i] = r1[i]; }
            mm2<18, 36>(sm.wr1, hA, hB, accR);
        }
        __syncthreads();
        statpair(sm, t, 36, 2);
        __syncthreads();
        scpair(sm, t, 36, 2, sm.g2v, sm.be2v, sm.a2v, 0);
        __syncthreads();
        if (isNode) {
            const ull* ouA = (const ull*)oA; const ull* ouB = (const ull*)oB;
            const ull* SuA = (const ull*)sm.redS;        const ull* CuA = (const ull*)sm.redC;
            const ull* SuB = (const ull*)&sm.redS[36];   const ull* CuB = (const ull*)&sm.redC[36];
            #pragma unroll
            for (int i = 0; i < 18; i++) {
                haU[i] = fadd2(ffma2(ouA[i], SuA[i], CuA[i]), accR[i]);
                hbU[i] = fadd2(ffma2(ouB[i], SuB[i], CuB[i]), accR[18 + i]);
            }
        }
        __syncthreads();

        // ========== Layer 3 (36->72): merged single pipeline ================
        if (isNode) {
            gatherU<18>(hU, haU, haU + AOFFU, nbU, dnb2, dd);
            gatherU<18>(hU + GBU, hbU, hbU + AOFFU, nbU, dnb2, dd);
            {
                ull acc[36];
                const ull* b3 = (const ull*)&sm.bc3[0];
                #pragma unroll
                for (int i = 0; i < 18; i++) { acc[i] = b3[i]; acc[18 + i] = b3[i]; }
                mm2<36, 72>(sm.wc3, hA + AOFF, hB + AOFF, acc);
                ull* ouA = (ull*)oA; ull* ouB = (ull*)oB;
                #pragma unroll
                for (int i = 0; i < 18; i++) { ouA[i] = acc[i]; ouB[i] = acc[18 + i]; }
            }
            {
                ull acc[36];
                const ull* b3 = (const ull*)&sm.bc3[36];
                #pragma unroll
                for (int i = 0; i < 18; i++) { acc[i] = b3[i]; acc[18 + i] = b3[i]; }
                mm2<36, 72>(sm.wc3 + 36, hA + AOFF, hB + AOFF, acc);
                ull* gAo = haU + AOFFU; ull* gBo = hbU + AOFFU;
                #pragma unroll
                for (int i = 0; i < 18; i++) { gAo[i] = acc[i]; gBo[i] = acc[18 + i]; }
            }
        }
        __syncthreads();
        // single 72-wide stats: A threads [0,72), B threads [96,168)
        if (t < 72) {
            const float* pp = (t < 36) ? (sm.out + t) : (sm.h + AOFF + (t - 36));
            const int str = (t < 36) ? OSF : HSF;
            float s = 0.f, s2 = 0.f;
            for (int n = 0; n < SN; n++) { float v = pp[n * str]; s += v; s2 = fmaf(v, v, s2); }
            sm.redP[t] = s; sm.redQ[t] = s2;
        } else if (t >= 96 && t < 168) {
            const int f = t - 96;
            const float* pp = (f < 36) ? (sm.out + OB + f) : (sm.h + GB + AOFF + (f - 36));
            const int str = (f < 36) ? OSF : HSF;
            float s = 0.f, s2 = 0.f;
            for (int n = 0; n < SN; n++) { float v = pp[n * str]; s += v; s2 = fmaf(v, v, s2); }
            sm.redP[t] = s; sm.redQ[t] = s2;
        }
        __syncthreads();
        if (t < 72) {
            float m = sm.redP[t] * invS, af = sm.a3v[t];
            float var = sm.redQ[t] * invS - m * m * af * (2.0f - af);
            float S = sm.g3v[t] * rsqrtf(var + EPSV);
            sm.redS[t] = S; sm.redC[t] = sm.be3v[t] - af * m * S;
        } else if (t >= 96 && t < 168) {
            const int f = t - 96;
            float m = sm.redP[t] * invS, af = sm.a3v[f];
            float var = sm.redQ[t] * invS - m * m * af * (2.0f - af);
            float S = sm.g3v[f] * rsqrtf(var + EPSV);
            sm.redS[72 + f] = S; sm.redC[72 + f] = sm.be3v[f] - af * m * S;
        }
        __syncthreads();
        // resid + apply, both halves
        if (isNode) {
            {
                const ull* r2 = (const ull*)&sm.br2[0];
                #pragma unroll
                for (int i = 0; i < 18; i++) { accR[i] = r2[i]; accR[18 + i] = r2[i]; }
                mm2<36, 72>(sm.wr2, hA, hB, accR);
                ull* ouA = (ull*)oA; ull* ouB = (ull*)oB;
                const ull* SA = (const ull*)sm.redS;         const ull* CA = (const ull*)sm.redC;
                const ull* SB = (const ull*)&sm.redS[72];    const ull* CB = (const ull*)&sm.redC[72];
                #pragma unroll
                for (int i = 0; i < 18; i++) {
                    ouA[i] = fadd2(ffma2(ouA[i], SA[i], CA[i]), accR[i]);
                    ouB[i] = fadd2(ffma2(ouB[i], SB[i], CB[i]), accR[18 + i]);
                }
            }
            {
                const ull* r2 = (const ull*)&sm.br2[36];
                #pragma unroll
                for (int i = 0; i < 18; i++) { accR[i] = r2[i]; accR[18 + i] = r2[i]; }
                mm2<36, 72>(sm.wr2 + 36, hA, hB, accR);
                ull* gAo = haU + AOFFU; ull* gBo = hbU + AOFFU;
                const ull* SA = (const ull*)&sm.redS[36];    const ull* CA = (const ull*)&sm.redC[36];
                const ull* SB = (const ull*)&sm.redS[108];   const ull* CB = (const ull*)&sm.redC[108];
                #pragma unroll
                for (int i = 0; i < 18; i++) {
                    gAo[i] = fadd2(ffma2(gAo[i], SA[i], CA[i]), accR[i]);
                    gBo[i] = fadd2(ffma2(gBo[i], SB[i], CB[i]), accR[18 + i]);
                }
            }
        }
        __syncthreads();
        // single pool straight to g_pooled
        if (t < 72) {
            const float* pp = (t < 36) ? (sm.out + t) : (sm.h + AOFF + (t - 36));
            const int str = (t < 36) ? OSF : HSF;
            float m = -INFINITY;
            for (int n = 0; n < SN; n++) m = fmaxf(m, pp[n * str]);
            g_pooled[gA * 72 + t] = m;
        } else if (t >= 96 && t < 168) {
            const int f = t - 96;
            const float* pp = (f < 36) ? (sm.out + OB + f) : (sm.h + GB + AOFF + (f - 36));
            const int str = (f < 36) ? OSF : HSF;
            float m = -INFINITY;
            for (int n = 0; n < SN; n++) m = fmaxf(m, pp[n * str]);
            g_pooled[gB2 * 72 + f] = m;
        }
        __syncthreads();
    }
}

// ---------------------------------------------------------------------------
// MLP: grid 148, each CTA loops over tiles (halves weight L2 traffic).
// ---------------------------------------------------------------------------
struct __align__(16) MSmem {
    ull rowsT[72][5];
    ull z1T[512][5];
    ull z2P[256][5];
    ull z2T[256][5];
};

__global__ void __launch_bounds__(512) mlp_kernel(
    const float* __restrict__ wf1, const float* __restrict__ bf1,
    const float* __restrict__ wf2, const float* __restrict__ bf2,
    const float* __restrict__ wm, const float* __restrict__ bm,
    const float* __restrict__ wl, const float* __restrict__ bl,
    float* __restrict__ out)
{
    extern __shared__ char smraw[];
    MSmem& sm = *reinterpret_cast<MSmem*>(smraw);
    const int tid = threadIdx.x;

    for (int tile = blockIdx.x; tile < NG / 8; tile += GRID) {
        const int r0 = tile * 8;

        {
            float* rf = (float*)sm.rowsT;
            for (int i = tid; i < 8 * 72; i += 512) {
                const int k = i / 8, r = i % 8;
                rf[k * 10 + r] = g_pooled[(r0 + r) * 72 + k];
            }
        }
        __syncthreads();

        {
            const int j = tid;
            const float b = __ldg(bf1 + j);
            ull acc[4];
            #pragma unroll
            for (int i = 0; i < 4; i++) acc[i] = pk2(b, b);
            #pragma unroll 8
            for (int k = 0; k < 72; k++) {
                const float w = __ldg(wf1 + k * 512 + j);
                const ull ww = pk2(w, w);
                const ull* rw = sm.rowsT[k];
                #pragma unroll
                for (int i = 0; i < 4; i++) acc[i] = ffma2(ww, rw[i], acc[i]);
            }
            #pragma unroll
            for (int i = 0; i < 4; i++) {
                float2 v = upk2(acc[i]);
                sm.z1T[j][i] = pk2(fmaxf(v.x, 0.f), fmaxf(v.y, 0.f));
            }
        }
        __syncthreads();

        {
            const int jj = tid & 255, half = tid >> 8;
            ull acc[4];
            if (half == 0) {
                const float b = __ldg(bf2 + jj);
                #pragma unroll
                for (int i = 0; i < 4; i++) acc[i] = pk2(b, b);
            } else {
                #pragma unroll
                for (int i = 0; i < 4; i++) acc[i] = 0ull;
            }
            const int k0 = half * 256;
            #pragma unroll 8
            for (int kk = 0; kk < 256; kk++) {
                const int k = k0 + kk;
                const float w = __ldg(wf2 + k * 256 + jj);
                const ull ww = pk2(w, w);
                const ull* zw = sm.z1T[k];
                #pragma unroll
                for (int i = 0; i < 4; i++) acc[i] = ffma2(ww, zw[i], acc[i]);
            }
            if (half == 1) {
                #pragma unroll
                for (int i = 0; i < 4; i++) sm.z2P[jj][i] = acc[i];
            }
            __syncthreads();
            if (half == 0) {
                #pragma unroll
                for (int i = 0; i < 4; i++) {
                    float2 v = upk2(fadd2(acc[i], sm.z2P[jj][i]));
                    sm.z2T[jj][i] = pk2(fmaxf(v.x, 0.f), fmaxf(v.y, 0.f));
                }
            }
            __syncthreads();
        }

        {
            const int w = tid >> 5, lane = tid & 31;
            if (w < 8) {
                const int rp = w >> 1, hi = w & 1;
                float smv = 0.f, slv = 0.f;
                #pragma unroll 4
                for (int k = lane; k < 256; k += 32) {
                    float2 v2 = upk2(sm.z2T[k][rp]);
                    const float v = hi ? v2.y : v2.x;
                    smv = fmaf(v, __ldg(wm + k), smv);
                    slv = fmaf(v, __ldg(wl + k), slv);
                }
                #pragma unroll
                for (int o = 16; o > 0; o >>= 1) {
                    smv += __shfl_xor_sync(0xffffffffu, smv, o);
                    slv += __shfl_xor_sync(0xffffffffu, slv, o);
                }
                if (lane == 0) {
                    out[r0 + w] = smv + __ldg(bm);
                    const float ls = tanhf(slv + __ldg(bl));
                    out[NG + r0 + w] = LSMIN + 0.5f * (LSMAX - LSMIN) * (ls + 1.0f);
                }
            }
        }
        __syncthreads();   // z2T/rowsT reuse next tile
    }
}

// ---------------------------------------------------------------------------
extern "C" void kernel_launch(void* const* d_in, const int* in_sizes, int n_in,
                              void* d_out, int out_size)
{
    const int*   x    = (const int*)d_in[0];
    const float* emb  = (const float*)d_in[2];
    const float* wc1  = (const float*)d_in[3];
    const float* bc1  = (const float*)d_in[4];
    const float* wc2  = (const float*)d_in[5];
    const float* bc2  = (const float*)d_in[6];
    const float* wc3  = (const float*)d_in[7];
    const float* bc3  = (const float*)d_in[8];
    const float* wr1  = (const float*)d_in[9];
    const float* br1  = (const float*)d_in[10];
    const float* wr2  = (const float*)d_in[11];
    const float* br2  = (const float*)d_in[12];
    const float* g1   = (const float*)d_in[13];
    const float* be1  = (const float*)d_in[14];
    const float* a1   = (const float*)d_in[15];
    const float* g2   = (const float*)d_in[16];
    const float* be2  = (const float*)d_in[17];
    const float* a2   = (const float*)d_in[18];
    const float* g3   = (const float*)d_in[19];
    const float* be3  = (const float*)d_in[20];
    const float* a3   = (const float*)d_in[21];
    const float* wf1  = (const float*)d_in[22];
    const float* bf1  = (const float*)d_in[23];
    const float* wf2  = (const float*)d_in[24];
    const float* bf2  = (const float*)d_in[25];
    const float* wm   = (const float*)d_in[26];
    const float* bm   = (const float*)d_in[27];
    const float* wl   = (const float*)d_in[28];
    const float* bl   = (const float*)d_in[29];
    float* out = (float*)d_out;

    cudaFuncSetAttribute(gnn_kernel, cudaFuncAttributeMaxDynamicSharedMemorySize,
                         (int)sizeof(Smem));
    cudaFuncSetAttribute(mlp_kernel, cudaFuncAttributeMaxDynamicSharedMemorySize,
                         (int)sizeof(MSmem));

    gnn_kernel<<<GRID, NT, sizeof(Smem)>>>(
        x, emb, wc1, bc1, wc2, bc2, wc3, bc3, wr1, br1, wr2, br2,
        g1, be1, a1, g2, be2, a2, g3, be3, a3);

    mlp_kernel<<<GRID, 512, sizeof(MSmem)>>>(
        wf1, bf1, wf2, bf2, wm, bm, wl, bl, out);
}

// round 13
// speedup vs baseline: 1.0287x; 1.0287x over previous
#include <cuda_runtime.h>
#include <math.h>

#define NBOARD 13
#define SN 169
#define NG 2048
#define NT 192
#define GRID 148
#define EPSV 1e-5f
#define LSMIN -5.0f
#define LSMAX 2.0f

#define HSF 78            // h row stride (floats): FEAT [0,36), AGG [40,76)
#define HSU 39            // in ull (odd -> conflict-free 8B accesses)
#define AOFF 40
#define AOFFU 20
#define OSF 38            // out row stride (19 ull, odd)
#define GB (SN * HSF)
#define GBU (SN * HSU)
#define OB (SN * OSF)

typedef unsigned long long ull;

__device__ __forceinline__ ull pk2(float x, float y) {
    ull r; asm("mov.b64 %0, {%1,%2};" : "=l"(r) : "f"(x), "f"(y)); return r;
}
__device__ __forceinline__ float2 upk2(ull a) {
    float2 v; asm("mov.b64 {%0,%1}, %2;" : "=f"(v.x), "=f"(v.y) : "l"(a)); return v;
}
__device__ __forceinline__ ull ffma2(ull a, ull b, ull c) {
    ull d; asm("fma.rn.f32x2 %0, %1, %2, %3;" : "=l"(d) : "l"(a), "l"(b), "l"(c)); return d;
}
__device__ __forceinline__ ull fadd2(ull a, ull b) {
    ull d; asm("add.rn.f32x2 %0, %1, %2;" : "=l"(d) : "l"(a), "l"(b)); return d;
}
__device__ __forceinline__ ull fmul2(ull a, ull b) {
    ull d; asm("mul.rn.f32x2 %0, %1, %2;" : "=l"(d) : "l"(a), "l"(b)); return d;
}

__device__ float g_pooled[NG * 72];

struct __align__(16) Smem {
    float wc3[36 * 72];
    float wr2[36 * 72];
    float wc2[18 * 36];
    float wr1[18 * 36];
    float E1[56];             // emb @ wc1
    float embs[56];
    float bc1[18], bc2[36], bc3[72];
    float br1[36], br2[72];
    float g1v[18], be1v[18], a1v[18];
    float g2v[36], be2v[36], a2v[36];
    float g3v[72], be3v[72], a3v[72];
    float redP[192], redQ[192];
    float redS[144], redC[144];
    float dis[170];
    float h[2 * SN * HSF];
    float out[2 * SN * OSF];
};

__device__ __forceinline__ void cp_sm(float* dst, const float* src, int n, int t) {
    for (int i = t; i < n; i += NT) dst[i] = src[i];
}

// packed gather: WU ull features from own row + 6 neighbors (conflict-free)
template<int WU>
__device__ __forceinline__ void gatherU(const ull* base, const ull* own, ull* dst,
                                        const int* nbU, const ull* dnb2, ull dd) {
    #pragma unroll 2
    for (int k = 0; k < WU; k++) {
        ull a = fmul2(own[k], dd);
        #pragma unroll
        for (int j = 0; j < 6; j++) a = ffma2(dnb2[j], base[nbU[j] + k], a);
        dst[k] = fmul2(a, dd);
    }
}

// acc[0:18) += inA @ W ; acc[18:36) += inB @ W (36-wide output slice), W in smem
template<int K, int RS>
__device__ __forceinline__ void mm2(const float* W0, const float* inA, const float* inB, ull* acc) {
    #pragma unroll 2
    for (int k = 0; k < K; k++) {
        const float aA = inA[k], aB = inB[k];
        const ull qA = pk2(aA, aA), qB = pk2(aB, aB);
        const ulonglong2* w = (const ulonglong2*)(W0 + k * RS);
        #pragma unroll
        for (int jv = 0; jv < 9; jv++) {
            ulonglong2 ww = w[jv];
            acc[2 * jv]      = ffma2(qA, ww.x, acc[2 * jv]);
            acc[2 * jv + 1]  = ffma2(qA, ww.y, acc[2 * jv + 1]);
            acc[18 + 2 * jv]     = ffma2(qB, ww.x, acc[18 + 2 * jv]);
            acc[18 + 2 * jv + 1] = ffma2(qB, ww.y, acc[18 + 2 * jv + 1]);
        }
    }
}

__device__ __forceinline__ void statpair(Smem& sm, int t, int Wf, int NS) {
    if (t < Wf * NS) {
        const int f = t % Wf, sI = t / Wf;
        float s = 0.f, s2 = 0.f;
        const float* pp = sm.out + f;
        for (int n = sI; n < SN; n += NS) { float v = pp[n * OSF]; s += v; s2 = fmaf(v, v, s2); }
        sm.redP[t] = s; sm.redQ[t] = s2;
    } else if (t >= 96 && t < 96 + Wf * NS) {
        const int u = t - 96, f = u % Wf, sI = u / Wf;
        float s = 0.f, s2 = 0.f;
        const float* pp = sm.out + OB + f;
        for (int n = sI; n < SN; n += NS) { float v = pp[n * OSF]; s += v; s2 = fmaf(v, v, s2); }
        sm.redP[t] = s; sm.redQ[t] = s2;
    }
}

__device__ __forceinline__ void scpair(Smem& sm, int t, int Wf, int NS,
                                       const float* gv, const float* bev, const float* av, int poff) {
    const float invS = 1.0f / (float)SN;
    if (t < Wf) {
        float s = 0.f, s2 = 0.f;
        for (int i = 0; i < NS; i++) { s += sm.redP[t + i * Wf]; s2 += sm.redQ[t + i * Wf]; }
        float m = s * invS, af = av[poff + t];
        float var = s2 * invS - m * m * af * (2.0f - af);
        float S = gv[poff + t] * rsqrtf(var + EPSV);
        sm.redS[t] = S; sm.redC[t] = bev[poff + t] - af * m * S;
    } else if (t >= 96 && t < 96 + Wf) {
        const int f = t - 96;
        float s = 0.f, s2 = 0.f;
        for (int i = 0; i < NS; i++) { s += sm.redP[96 + f + i * Wf]; s2 += sm.redQ[96 + f + i * Wf]; }
        float m = s * invS, af = av[poff + f];
        float var = s2 * invS - m * m * af * (2.0f - af);
        float S = gv[poff + f] * rsqrtf(var + EPSV);
        sm.redS[36 + f] = S; sm.redC[36 + f] = bev[poff + f] - af * m * S;
    }
}

__global__ void __launch_bounds__(NT) gnn_kernel(
    const int* __restrict__ x,
    const float* __restrict__ emb,
    const float* __restrict__ wc1, const float* __restrict__ bc1,
    const float* __restrict__ wc2, const float* __restrict__ bc2,
    const float* __restrict__ wc3, const float* __restrict__ bc3,
    const float* __restrict__ wr1, const float* __restrict__ br1,
    const float* __restrict__ wr2, const float* __restrict__ br2,
    const float* __restrict__ g1, const float* __restrict__ be1, const float* __restrict__ a1,
    const float* __restrict__ g2, const float* __restrict__ be2, const float* __restrict__ a2,
    const float* __restrict__ g3, const float* __restrict__ be3, const float* __restrict__ a3)
{
    extern __shared__ char smraw[];
    Smem& sm = *reinterpret_cast<Smem*>(smraw);
    const int t = threadIdx.x;
    const bool isNode = (t < SN);
    ull* const hU = (ull*)sm.h;
    const float invS = 1.0f / (float)SN;

    cp_sm(sm.wc3, wc3, 36 * 72, t);
    cp_sm(sm.wr2, wr2, 36 * 72, t);
    cp_sm(sm.wc2, wc2, 18 * 36, t);
    cp_sm(sm.wr1, wr1, 18 * 36, t);
    cp_sm(sm.bc1, bc1, 18, t);  cp_sm(sm.bc2, bc2, 36, t);  cp_sm(sm.bc3, bc3, 72, t);
    cp_sm(sm.br1, br1, 36, t);  cp_sm(sm.br2, br2, 72, t);
    cp_sm(sm.g1v, g1, 18, t);   cp_sm(sm.be1v, be1, 18, t); cp_sm(sm.a1v, a1, 18, t);
    cp_sm(sm.g2v, g2, 36, t);   cp_sm(sm.be2v, be2, 36, t); cp_sm(sm.a2v, a2, 36, t);
    cp_sm(sm.g3v, g3, 72, t);   cp_sm(sm.be3v, be3, 72, t); cp_sm(sm.a3v, a3, 72, t);
    cp_sm(sm.embs, emb, 3 * 18, t);

    if (t < 54) {
        const int e = t / 18, j = t % 18;
        float s = 0.f;
        #pragma unroll
        for (int k = 0; k < 18; k++) s += emb[e * 18 + k] * wc1[k * 18 + j];
        sm.E1[e * 18 + j] = s;
    }

    int nbU[6], nbi[6];
    ull dnb2[6];
    float disn = 0.f;
    if (isNode) {
        const int r = t / NBOARD, c = t % NBOARD;
        const int drr[6] = { -1, 1, 0, 0, -1, 1 };
        const int dcc[6] = { 0, 0, -1, 1, 1, -1 };
        int deg = 1;
        #pragma unroll
        for (int j = 0; j < 6; j++) {
            int rr = r + drr[j], cc = c + dcc[j];
            if (rr >= 0 && rr < NBOARD && cc >= 0 && cc < NBOARD) { nbi[j] = rr * NBOARD + cc; deg++; }
            else nbi[j] = t;
            nbU[j] = nbi[j] * HSU;
        }
        disn = rsqrtf((float)deg);
        sm.dis[t] = disn;
    }
    __syncthreads();
    if (isNode) {
        #pragma unroll
        for (int j = 0; j < 6; j++) {
            const float d = (nbi[j] == t) ? 0.f : sm.dis[nbi[j]];
            dnb2[j] = pk2(d, d);
        }
    }
    __syncthreads();

    const ull dd = pk2(disn, disn);
    float* const hA = sm.h + t * HSF;
    float* const hB = sm.h + GB + t * HSF;
    ull* const haU = hU + t * HSU;
    ull* const hbU = hU + GBU + t * HSU;
    float* const oA = sm.out + t * OSF;
    float* const oB = sm.out + OB + t * OSF;

    for (int p = blockIdx.x; p < NG / 2; p += GRID) {
        const int gA = 2 * p, gB2 = 2 * p + 1;

        // ---- lookup ----
        ull h0A[9], h0B[9];
        if (isNode) {
            const int xa = x[gA * SN + t];
            const int xb = x[gB2 * SN + t];
            const ull* ea = (const ull*)&sm.embs[xa * 18];
            const ull* eb = (const ull*)&sm.embs[xb * 18];
            const ull* fa = (const ull*)&sm.E1[xa * 18];
            const ull* fb = (const ull*)&sm.E1[xb * 18];
            #pragma unroll
            for (int i = 0; i < 9; i++) { h0A[i] = ea[i]; h0B[i] = eb[i]; haU[i] = fa[i]; hbU[i] = fb[i]; }
        }
        __syncthreads();

        // ================= Layer 1: conv = gather(E1x) + bc1 ================
        if (isNode) {
            const ull* b1 = (const ull*)sm.bc1;
            ull aU[9];
            gatherU<9>(hU, haU, aU, nbU, dnb2, dd);
            ull* ouA = (ull*)oA;
            #pragma unroll
            for (int i = 0; i < 9; i++) ouA[i] = fadd2(aU[i], b1[i]);
            gatherU<9>(hU + GBU, hbU, aU, nbU, dnb2, dd);
            ull* ouB = (ull*)oB;
            #pragma unroll
            for (int i = 0; i < 9; i++) ouB[i] = fadd2(aU[i], b1[i]);
        }
        __syncthreads();
        statpair(sm, t, 18, 5);
        __syncthreads();
        scpair(sm, t, 18, 5, sm.g1v, sm.be1v, sm.a1v, 0);
        __syncthreads();
        if (isNode) {
            const ull* ouA = (const ull*)oA; const ull* ouB = (const ull*)oB;
            const ull* SuA = (const ull*)sm.redS;        const ull* CuA = (const ull*)sm.redC;
            const ull* SuB = (const ull*)&sm.redS[36];   const ull* CuB = (const ull*)&sm.redC[36];
            #pragma unroll
            for (int i = 0; i < 9; i++) {
                haU[i] = fadd2(ffma2(ouA[i], SuA[i], CuA[i]), h0A[i]);
                hbU[i] = fadd2(ffma2(ouB[i], SuB[i], CuB[i]), h0B[i]);
            }
        }
        __syncthreads();

        // ================= Layer 2 (18->36) =================================
        ull accR[36];
        if (isNode) {
            gatherU<9>(hU, haU, haU + AOFFU, nbU, dnb2, dd);
            gatherU<9>(hU + GBU, hbU, hbU + AOFFU, nbU, dnb2, dd);
            ull acc[36];
            const ull* b2 = (const ull*)sm.bc2;
            #pragma unroll
            for (int i = 0; i < 18; i++) { acc[i] = b2[i]; acc[18 + i] = b2[i]; }
            mm2<18, 36>(sm.wc2, hA + AOFF, hB + AOFF, acc);
            ull* ouA = (ull*)oA; ull* ouB = (ull*)oB;
            #pragma unroll
            for (int i = 0; i < 18; i++) { ouA[i] = acc[i]; ouB[i] = acc[18 + i]; }
            const ull* r1 = (const ull*)sm.br1;
            #pragma unroll
            for (int i = 0; i < 18; i++) { accR[i] = r1[i]; accR[18 + i] = r1[i]; }
            mm2<18, 36>(sm.wr1, hA, hB, accR);
        }
        __syncthreads();
        statpair(sm, t, 36, 2);
        __syncthreads();
        scpair(sm, t, 36, 2, sm.g2v, sm.be2v, sm.a2v, 0);
        __syncthreads();
        if (isNode) {
            const ull* ouA = (const ull*)oA; const ull* ouB = (const ull*)oB;
            const ull* SuA = (const ull*)sm.redS;        const ull* CuA = (const ull*)sm.redC;
            const ull* SuB = (const ull*)&sm.redS[36];   const ull* CuB = (const ull*)&sm.redC[36];
            #pragma unroll
            for (int i = 0; i < 18; i++) {
                haU[i] = fadd2(ffma2(ouA[i], SuA[i], CuA[i]), accR[i]);
                hbU[i] = fadd2(ffma2(ouB[i], SuB[i], CuB[i]), accR[18 + i]);
            }
        }
        __syncthreads();

        // ========== Layer 3 (36->72): merged single pipeline ================
        if (isNode) {
            gatherU<18>(hU, haU, haU + AOFFU, nbU, dnb2, dd);
            gatherU<18>(hU + GBU, hbU, hbU + AOFFU, nbU, dnb2, dd);
            {
                ull acc[36];
                const ull* b3 = (const ull*)&sm.bc3[0];
                #pragma unroll
                for (int i = 0; i < 18; i++) { acc[i] = b3[i]; acc[18 + i] = b3[i]; }
                mm2<36, 72>(sm.wc3, hA + AOFF, hB + AOFF, acc);
                ull* ouA = (ull*)oA; ull* ouB = (ull*)oB;
                #pragma unroll
                for (int i = 0; i < 18; i++) { ouA[i] = acc[i]; ouB[i] = acc[18 + i]; }
            }
            {
                ull acc[36];
                const ull* b3 = (const ull*)&sm.bc3[36];
                #pragma unroll
                for (int i = 0; i < 18; i++) { acc[i] = b3[i]; acc[18 + i] = b3[i]; }
                mm2<36, 72>(sm.wc3 + 36, hA + AOFF, hB + AOFF, acc);
                ull* gAo = haU + AOFFU; ull* gBo = hbU + AOFFU;
                #pragma unroll
                for (int i = 0; i < 18; i++) { gAo[i] = acc[i]; gBo[i] = acc[18 + i]; }
            }
        }
        __syncthreads();
        // single 72-wide stats: A threads [0,72), B threads [96,168)
        if (t < 72) {
            const float* pp = (t < 36) ? (sm.out + t) : (sm.h + AOFF + (t - 36));
            const int str = (t < 36) ? OSF : HSF;
            float s = 0.f, s2 = 0.f;
            for (int n = 0; n < SN; n++) { float v = pp[n * str]; s += v; s2 = fmaf(v, v, s2); }
            sm.redP[t] = s; sm.redQ[t] = s2;
        } else if (t >= 96 && t < 168) {
            const int f = t - 96;
            const float* pp = (f < 36) ? (sm.out + OB + f) : (sm.h + GB + AOFF + (f - 36));
            const int str = (f < 36) ? OSF : HSF;
            float s = 0.f, s2 = 0.f;
            for (int n = 0; n < SN; n++) { float v = pp[n * str]; s += v; s2 = fmaf(v, v, s2); }
            sm.redP[t] = s; sm.redQ[t] = s2;
        }
        __syncthreads();
        if (t < 72) {
            float m = sm.redP[t] * invS, af = sm.a3v[t];
            float var = sm.redQ[t] * invS - m * m * af * (2.0f - af);
            float S = sm.g3v[t] * rsqrtf(var + EPSV);
            sm.redS[t] = S; sm.redC[t] = sm.be3v[t] - af * m * S;
        } else if (t >= 96 && t < 168) {
            const int f = t - 96;
            float m = sm.redP[t] * invS, af = sm.a3v[f];
            float var = sm.redQ[t] * invS - m * m * af * (2.0f - af);
            float S = sm.g3v[f] * rsqrtf(var + EPSV);
            sm.redS[72 + f] = S; sm.redC[72 + f] = sm.be3v[f] - af * m * S;
        }
        __syncthreads();
        // resid + apply, both halves
        if (isNode) {
            {
                const ull* r2 = (const ull*)&sm.br2[0];
                #pragma unroll
                for (int i = 0; i < 18; i++) { accR[i] = r2[i]; accR[18 + i] = r2[i]; }
                mm2<36, 72>(sm.wr2, hA, hB, accR);
                ull* ouA = (ull*)oA; ull* ouB = (ull*)oB;
                const ull* SA = (const ull*)sm.redS;         const ull* CA = (const ull*)sm.redC;
                const ull* SB = (const ull*)&sm.redS[72];    const ull* CB = (const ull*)&sm.redC[72];
                #pragma unroll
                for (int i = 0; i < 18; i++) {
                    ouA[i] = fadd2(ffma2(ouA[i], SA[i], CA[i]), accR[i]);
                    ouB[i] = fadd2(ffma2(ouB[i], SB[i], CB[i]), accR[18 + i]);
                }
            }
            {
                const ull* r2 = (const ull*)&sm.br2[36];
                #pragma unroll
                for (int i = 0; i < 18; i++) { accR[i] = r2[i]; accR[18 + i] = r2[i]; }
                mm2<36, 72>(sm.wr2 + 36, hA, hB, accR);
                ull* gAo = haU + AOFFU; ull* gBo = hbU + AOFFU;
                const ull* SA = (const ull*)&sm.redS[36];    const ull* CA = (const ull*)&sm.redC[36];
                const ull* SB = (const ull*)&sm.redS[108];   const ull* CB = (const ull*)&sm.redC[108];
                #pragma unroll
                for (int i = 0; i < 18; i++) {
                    gAo[i] = fadd2(ffma2(gAo[i], SA[i], CA[i]), accR[i]);
                    gBo[i] = fadd2(ffma2(gBo[i], SB[i], CB[i]), accR[18 + i]);
                }
            }
        }
        __syncthreads();
        // single pool straight to g_pooled
        if (t < 72) {
            const float* pp = (t < 36) ? (sm.out + t) : (sm.h + AOFF + (t - 36));
            const int str = (t < 36) ? OSF : HSF;
            float m = -INFINITY;
            for (int n = 0; n < SN; n++) m = fmaxf(m, pp[n * str]);
            g_pooled[gA * 72 + t] = m;
        } else if (t >= 96 && t < 168) {
            const int f = t - 96;
            const float* pp = (f < 36) ? (sm.out + OB + f) : (sm.h + GB + AOFF + (f - 36));
            const int str = (f < 36) ? OSF : HSF;
            float m = -INFINITY;
            for (int n = 0; n < SN; n++) m = fmaxf(m, pp[n * str]);
            g_pooled[gB2 * 72 + f] = m;
        }
        __syncthreads();
    }
}

// ---------------------------------------------------------------------------
// MLP (R8/R11 exact, 35.9us measured): TM=8, grid 256, 512 threads, split-k z2.
// ---------------------------------------------------------------------------
struct __align__(16) MSmem {
    ull rowsT[72][5];
    ull z1T[512][5];
    ull z2P[256][5];
    ull z2T[256][5];
};

__global__ void __launch_bounds__(512, 2) mlp_kernel(
    const float* __restrict__ wf1, const float* __restrict__ bf1,
    const float* __restrict__ wf2, const float* __restrict__ bf2,
    const float* __restrict__ wm, const float* __restrict__ bm,
    const float* __restrict__ wl, const float* __restrict__ bl,
    float* __restrict__ out)
{
    extern __shared__ char smraw[];
    MSmem& sm = *reinterpret_cast<MSmem*>(smraw);
    const int tid = threadIdx.x;
    const int r0 = blockIdx.x * 8;

    {
        float* rf = (float*)sm.rowsT;
        for (int i = tid; i < 8 * 72; i += 512) {
            const int k = i / 8, r = i % 8;
            rf[k * 10 + r] = g_pooled[(r0 + r) * 72 + k];
        }
    }
    __syncthreads();

    {
        const int j = tid;
        const float b = __ldg(bf1 + j);
        ull acc[4];
        #pragma unroll
        for (int i = 0; i < 4; i++) acc[i] = pk2(b, b);
        #pragma unroll 8
        for (int k = 0; k < 72; k++) {
            const float w = __ldg(wf1 + k * 512 + j);
            const ull ww = pk2(w, w);
            const ull* rw = sm.rowsT[k];
            #pragma unroll
            for (int i = 0; i < 4; i++) acc[i] = ffma2(ww, rw[i], acc[i]);
        }
        #pragma unroll
        for (int i = 0; i < 4; i++) {
            float2 v = upk2(acc[i]);
            sm.z1T[j][i] = pk2(fmaxf(v.x, 0.f), fmaxf(v.y, 0.f));
        }
    }
    __syncthreads();

    {
        const int jj = tid & 255, half = tid >> 8;
        ull acc[4];
        if (half == 0) {
            const float b = __ldg(bf2 + jj);
            #pragma unroll
            for (int i = 0; i < 4; i++) acc[i] = pk2(b, b);
        } else {
            #pragma unroll
            for (int i = 0; i < 4; i++) acc[i] = 0ull;
        }
        const int k0 = half * 256;
        #pragma unroll 8
        for (int kk = 0; kk < 256; kk++) {
            const int k = k0 + kk;
            const float w = __ldg(wf2 + k * 256 + jj);
            const ull ww = pk2(w, w);
            const ull* zw = sm.z1T[k];
            #pragma unroll
            for (int i = 0; i < 4; i++) acc[i] = ffma2(ww, zw[i], acc[i]);
        }
        if (half == 1) {
            #pragma unroll
            for (int i = 0; i < 4; i++) sm.z2P[jj][i] = acc[i];
        }
        __syncthreads();
        if (half == 0) {
            #pragma unroll
            for (int i = 0; i < 4; i++) {
                float2 v = upk2(fadd2(acc[i], sm.z2P[jj][i]));
                sm.z2T[jj][i] = pk2(fmaxf(v.x, 0.f), fmaxf(v.y, 0.f));
            }
        }
        __syncthreads();
    }

    {
        const int w = tid >> 5, lane = tid & 31;
        if (w < 8) {
            const int rp = w >> 1, hi = w & 1;
            float smv = 0.f, slv = 0.f;
            #pragma unroll 4
            for (int k = lane; k < 256; k += 32) {
                float2 v2 = upk2(sm.z2T[k][rp]);
                const float v = hi ? v2.y : v2.x;
                smv = fmaf(v, __ldg(wm + k), smv);
                slv = fmaf(v, __ldg(wl + k), slv);
            }
            #pragma unroll
            for (int o = 16; o > 0; o >>= 1) {
                smv += __shfl_xor_sync(0xffffffffu, smv, o);
                slv += __shfl_xor_sync(0xffffffffu, slv, o);
            }
            if (lane == 0) {
                out[r0 + w] = smv + __ldg(bm);
                const float ls = tanhf(slv + __ldg(bl));
                out[NG + r0 + w] = LSMIN + 0.5f * (LSMAX - LSMIN) * (ls + 1.0f);
            }
        }
    }
}

// ---------------------------------------------------------------------------
extern "C" void kernel_launch(void* const* d_in, const int* in_sizes, int n_in,
                              void* d_out, int out_size)
{
    const int*   x    = (const int*)d_in[0];
    const float* emb  = (const float*)d_in[2];
    const float* wc1  = (const float*)d_in[3];
    const float* bc1  = (const float*)d_in[4];
    const float* wc2  = (const float*)d_in[5];
    const float* bc2  = (const float*)d_in[6];
    const float* wc3  = (const float*)d_in[7];
    const float* bc3  = (const float*)d_in[8];
    const float* wr1  = (const float*)d_in[9];
    const float* br1  = (const float*)d_in[10];
    const float* wr2  = (const float*)d_in[11];
    const float* br2  = (const float*)d_in[12];
    const float* g1   = (const float*)d_in[13];
    const float* be1  = (const float*)d_in[14];
    const float* a1   = (const float*)d_in[15];
    const float* g2   = (const float*)d_in[16];
    const float* be2  = (const float*)d_in[17];
    const float* a2   = (const float*)d_in[18];
    const float* g3   = (const float*)d_in[19];
    const float* be3  = (const float*)d_in[20];
    const float* a3   = (const float*)d_in[21];
    const float* wf1  = (const float*)d_in[22];
    const float* bf1  = (const float*)d_in[23];
    const float* wf2  = (const float*)d_in[24];
    const float* bf2  = (const float*)d_in[25];
    const float* wm   = (const float*)d_in[26];
    const float* bm   = (const float*)d_in[27];
    const float* wl   = (const float*)d_in[28];
    const float* bl   = (const float*)d_in[29];
    float* out = (float*)d_out;

    cudaFuncSetAttribute(gnn_kernel, cudaFuncAttributeMaxDynamicSharedMemorySize,
                         (int)sizeof(Smem));
    cudaFuncSetAttribute(mlp_kernel, cudaFuncAttributeMaxDynamicSharedMemorySize,
                         (int)sizeof(MSmem));

    gnn_kernel<<<GRID, NT, sizeof(Smem)>>>(
        x, emb, wc1, bc1, wc2, bc2, wc3, bc3, wr1, br1, wr2, br2,
        g1, be1, a1, g2, be2, a2, g3, be3, a3);

    mlp_kernel<<<NG / 8, 512, sizeof(MSmem)>>>(
        wf1, bf1, wf2, bf2, wm, bm, wl, bl, out);
}

// round 14
// speedup vs baseline: 1.1185x; 1.0873x over previous
#include <cuda_runtime.h>
#include <math.h>

#define NBOARD 13
#define SN 169
#define NG 2048
#define NT 192
#define GGRID 296         // 2 CTAs per SM
#define EPSV 1e-5f
#define LSMIN -5.0f
#define LSMAX 2.0f

#define HSF 78            // h row stride (floats): FEAT [0,36), AGG [40,76)
#define HSU 39
#define AOFF 40
#define AOFFU 20
#define OSF 38

typedef unsigned long long ull;

__device__ __forceinline__ ull pk2(float x, float y) {
    ull r; asm("mov.b64 %0, {%1,%2};" : "=l"(r) : "f"(x), "f"(y)); return r;
}
__device__ __forceinline__ float2 upk2(ull a) {
    float2 v; asm("mov.b64 {%0,%1}, %2;" : "=f"(v.x), "=f"(v.y) : "l"(a)); return v;
}
__device__ __forceinline__ ull ffma2(ull a, ull b, ull c) {
    ull d; asm("fma.rn.f32x2 %0, %1, %2, %3;" : "=l"(d) : "l"(a), "l"(b), "l"(c)); return d;
}
__device__ __forceinline__ ull fadd2(ull a, ull b) {
    ull d; asm("add.rn.f32x2 %0, %1, %2;" : "=l"(d) : "l"(a), "l"(b)); return d;
}
__device__ __forceinline__ ull fmul2(ull a, ull b) {
    ull d; asm("mul.rn.f32x2 %0, %1, %2;" : "=l"(d) : "l"(a), "l"(b)); return d;
}

__device__ float g_pooled[NG * 72];

struct __align__(16) Smem {
    float wc3[36 * 72];
    float wr2[36 * 72];
    float wc2[18 * 36];
    float wr1[18 * 36];
    float E1[56];
    float embs[56];
    float bc1[18], bc2[36], bc3[72];
    float br1[36], br2[72];
    float g1v[18], be1v[18], a1v[18];
    float g2v[36], be2v[36], a2v[36];
    float g3v[72], be3v[72], a3v[72];
    float redP[192], redQ[192];
    float redS[72], redC[72];
    float dis[170];
    float h[SN * HSF];       // single graph
    float out[SN * OSF];
};

__device__ __forceinline__ void cp_sm(float* dst, const float* src, int n, int t) {
    for (int i = t; i < n; i += NT) dst[i] = src[i];
}

// packed gather (conflict-free: HSU=39 odd)
template<int WU>
__device__ __forceinline__ void gatherU(const ull* base, const ull* own, ull* dst,
                                        const int* nbU, const ull* dnb2, ull dd) {
    #pragma unroll 2
    for (int k = 0; k < WU; k++) {
        ull a = fmul2(own[k], dd);
        #pragma unroll
        for (int j = 0; j < 6; j++) a = ffma2(dnb2[j], base[nbU[j] + k], a);
        dst[k] = fmul2(a, dd);
    }
}

// acc[0:18) += in @ W (36-wide output slice), weights broadcast from smem
template<int K, int RS>
__device__ __forceinline__ void mm1(const float* W0, const float* in, ull* acc) {
    #pragma unroll 2
    for (int k = 0; k < K; k++) {
        const float a = in[k];
        const ull q = pk2(a, a);
        const ulonglong2* w = (const ulonglong2*)(W0 + k * RS);
        #pragma unroll
        for (int jv = 0; jv < 9; jv++) {
            ulonglong2 ww = w[jv];
            acc[2 * jv]     = ffma2(q, ww.x, acc[2 * jv]);
            acc[2 * jv + 1] = ffma2(q, ww.y, acc[2 * jv + 1]);
        }
    }
}

// stats over out rows: Wf features x NS stripes
__device__ __forceinline__ void stat1(Smem& sm, int t, int Wf, int NS) {
    if (t < Wf * NS) {
        const int f = t % Wf, sI = t / Wf;
        float s = 0.f, s2 = 0.f;
        const float* pp = sm.out + f;
        for (int n = sI; n < SN; n += NS) { float v = pp[n * OSF]; s += v; s2 = fmaf(v, v, s2); }
        sm.redP[t] = s; sm.redQ[t] = s2;
    }
}

__device__ __forceinline__ void sc1(Smem& sm, int t, int Wf, int NS,
                                    const float* gv, const float* bev, const float* av) {
    const float invS = 1.0f / (float)SN;
    if (t < Wf) {
        float s = 0.f, s2 = 0.f;
        for (int i = 0; i < NS; i++) { s += sm.redP[t + i * Wf]; s2 += sm.redQ[t + i * Wf]; }
        float m = s * invS, af = av[t];
        float var = s2 * invS - m * m * af * (2.0f - af);
        float S = gv[t] * rsqrtf(var + EPSV);
        sm.redS[t] = S; sm.redC[t] = bev[t] - af * m * S;
    }
}

__global__ void __launch_bounds__(NT, 2) gnn_kernel(
    const int* __restrict__ x,
    const float* __restrict__ emb,
    const float* __restrict__ wc1, const float* __restrict__ bc1,
    const float* __restrict__ wc2, const float* __restrict__ bc2,
    const float* __restrict__ wc3, const float* __restrict__ bc3,
    const float* __restrict__ wr1, const float* __restrict__ br1,
    const float* __restrict__ wr2, const float* __restrict__ br2,
    const float* __restrict__ g1, const float* __restrict__ be1, const float* __restrict__ a1,
    const float* __restrict__ g2, const float* __restrict__ be2, const float* __restrict__ a2,
    const float* __restrict__ g3, const float* __restrict__ be3, const float* __restrict__ a3)
{
    extern __shared__ char smraw[];
    Smem& sm = *reinterpret_cast<Smem*>(smraw);
    const int t = threadIdx.x;
    const bool isNode = (t < SN);
    ull* const hU = (ull*)sm.h;
    const float invS = 1.0f / (float)SN;

    cp_sm(sm.wc3, wc3, 36 * 72, t);
    cp_sm(sm.wr2, wr2, 36 * 72, t);
    cp_sm(sm.wc2, wc2, 18 * 36, t);
    cp_sm(sm.wr1, wr1, 18 * 36, t);
    cp_sm(sm.bc1, bc1, 18, t);  cp_sm(sm.bc2, bc2, 36, t);  cp_sm(sm.bc3, bc3, 72, t);
    cp_sm(sm.br1, br1, 36, t);  cp_sm(sm.br2, br2, 72, t);
    cp_sm(sm.g1v, g1, 18, t);   cp_sm(sm.be1v, be1, 18, t); cp_sm(sm.a1v, a1, 18, t);
    cp_sm(sm.g2v, g2, 36, t);   cp_sm(sm.be2v, be2, 36, t); cp_sm(sm.a2v, a2, 36, t);
    cp_sm(sm.g3v, g3, 72, t);   cp_sm(sm.be3v, be3, 72, t); cp_sm(sm.a3v, a3, 72, t);
    cp_sm(sm.embs, emb, 3 * 18, t);

    if (t < 54) {
        const int e = t / 18, j = t % 18;
        float s = 0.f;
        #pragma unroll
        for (int k = 0; k < 18; k++) s += emb[e * 18 + k] * wc1[k * 18 + j];
        sm.E1[e * 18 + j] = s;
    }

    int nbU[6], nbi[6];
    ull dnb2[6];
    float disn = 0.f;
    if (isNode) {
        const int r = t / NBOARD, c = t % NBOARD;
        const int drr[6] = { -1, 1, 0, 0, -1, 1 };
        const int dcc[6] = { 0, 0, -1, 1, 1, -1 };
        int deg = 1;
        #pragma unroll
        for (int j = 0; j < 6; j++) {
            int rr = r + drr[j], cc = c + dcc[j];
            if (rr >= 0 && rr < NBOARD && cc >= 0 && cc < NBOARD) { nbi[j] = rr * NBOARD + cc; deg++; }
            else nbi[j] = t;
            nbU[j] = nbi[j] * HSU;
        }
        disn = rsqrtf((float)deg);
        sm.dis[t] = disn;
    }
    __syncthreads();
    if (isNode) {
        #pragma unroll
        for (int j = 0; j < 6; j++) {
            const float d = (nbi[j] == t) ? 0.f : sm.dis[nbi[j]];
            dnb2[j] = pk2(d, d);
        }
    }
    __syncthreads();

    const ull dd = pk2(disn, disn);
    float* const hA = sm.h + t * HSF;
    ull* const haU = hU + t * HSU;
    float* const oA = sm.out + t * OSF;

    for (int g = blockIdx.x; g < NG; g += GGRID) {

        // ---- lookup: h <- E1[x], original embedding in regs ----
        ull h0A[9];
        if (isNode) {
            const int xa = x[g * SN + t];
            const ull* ea = (const ull*)&sm.embs[xa * 18];
            const ull* fa = (const ull*)&sm.E1[xa * 18];
            #pragma unroll
            for (int i = 0; i < 9; i++) { h0A[i] = ea[i]; haU[i] = fa[i]; }
        }
        __syncthreads();

        // ================= Layer 1: conv = gather(E1x) + bc1 ================
        if (isNode) {
            const ull* b1 = (const ull*)sm.bc1;
            ull aU[9];
            gatherU<9>(hU, haU, aU, nbU, dnb2, dd);
            ull* ouA = (ull*)oA;
            #pragma unroll
            for (int i = 0; i < 9; i++) ouA[i] = fadd2(aU[i], b1[i]);
        }
        __syncthreads();
        stat1(sm, t, 18, 10);
        __syncthreads();
        sc1(sm, t, 18, 10, sm.g1v, sm.be1v, sm.a1v);
        __syncthreads();
        if (isNode) {
            const ull* ouA = (const ull*)oA;
            const ull* Su = (const ull*)sm.redS;
            const ull* Cu = (const ull*)sm.redC;
            #pragma unroll
            for (int i = 0; i < 9; i++)
                haU[i] = fadd2(ffma2(ouA[i], Su[i], Cu[i]), h0A[i]);
        }
        __syncthreads();

        // ================= Layer 2 (18->36) =================================
        ull accR[18];
        if (isNode) {
            gatherU<9>(hU, haU, haU + AOFFU, nbU, dnb2, dd);
            ull acc[18];
            const ull* b2 = (const ull*)sm.bc2;
            #pragma unroll
            for (int i = 0; i < 18; i++) acc[i] = b2[i];
            mm1<18, 36>(sm.wc2, hA + AOFF, acc);
            ull* ouA = (ull*)oA;
            #pragma unroll
            for (int i = 0; i < 18; i++) ouA[i] = acc[i];
            const ull* r1 = (const ull*)sm.br1;
            #pragma unroll
            for (int i = 0; i < 18; i++) accR[i] = r1[i];
            mm1<18, 36>(sm.wr1, hA, accR);
        }
        __syncthreads();
        stat1(sm, t, 36, 5);
        __syncthreads();
        sc1(sm, t, 36, 5, sm.g2v, sm.be2v, sm.a2v);
        __syncthreads();
        if (isNode) {
            const ull* ouA = (const ull*)oA;
            const ull* Su = (const ull*)sm.redS;
            const ull* Cu = (const ull*)sm.redC;
            #pragma unroll
            for (int i = 0; i < 18; i++)
                haU[i] = fadd2(ffma2(ouA[i], Su[i], Cu[i]), accR[i]);
        }
        __syncthreads();

        // ========== Layer 3 (36->72): merged single pipeline ================
        // conv half0 -> out rows; conv half1 -> AGG region (dead after convs).
        if (isNode) {
            gatherU<18>(hU, haU, haU + AOFFU, nbU, dnb2, dd);
            {
                ull acc[18];
                const ull* b3 = (const ull*)&sm.bc3[0];
                #pragma unroll
                for (int i = 0; i < 18; i++) acc[i] = b3[i];
                mm1<36, 72>(sm.wc3, hA + AOFF, acc);
                ull* ouA = (ull*)oA;
                #pragma unroll
                for (int i = 0; i < 18; i++) ouA[i] = acc[i];
            }
            {
                ull acc[18];
                const ull* b3 = (const ull*)&sm.bc3[36];
                #pragma unroll
                for (int i = 0; i < 18; i++) acc[i] = b3[i];
                mm1<36, 72>(sm.wc3 + 36, hA + AOFF, acc);
                ull* gAo = haU + AOFFU;
                #pragma unroll
                for (int i = 0; i < 18; i++) gAo[i] = acc[i];
            }
        }
        __syncthreads();
        // 72-wide stats, 2 stripes (144 threads)
        if (t < 144) {
            const int f = t % 72, sI = t / 72;
            const float* pp = (f < 36) ? (sm.out + f) : (sm.h + AOFF + (f - 36));
            const int str = (f < 36) ? OSF : HSF;
            float s = 0.f, s2 = 0.f;
            for (int n = sI; n < SN; n += 2) { float v = pp[n * str]; s += v; s2 = fmaf(v, v, s2); }
            sm.redP[t] = s; sm.redQ[t] = s2;
        }
        __syncthreads();
        if (t < 72) {
            float s = sm.redP[t] + sm.redP[t + 72];
            float s2 = sm.redQ[t] + sm.redQ[t + 72];
            float m = s * invS, af = sm.a3v[t];
            float var = s2 * invS - m * m * af * (2.0f - af);
            float S = sm.g3v[t] * rsqrtf(var + EPSV);
            sm.redS[t] = S; sm.redC[t] = sm.be3v[t] - af * m * S;
        }
        __syncthreads();
        // resid + apply, both halves (FEAT region intact as input)
        if (isNode) {
            {
                ull aR[18];
                const ull* r2 = (const ull*)&sm.br2[0];
                #pragma unroll
                for (int i = 0; i < 18; i++) aR[i] = r2[i];
                mm1<36, 72>(sm.wr2, hA, aR);
                ull* ouA = (ull*)oA;
                const ull* SA = (const ull*)sm.redS;
                const ull* CA = (const ull*)sm.redC;
                #pragma unroll
                for (int i = 0; i < 18; i++)
                    ouA[i] = fadd2(ffma2(ouA[i], SA[i], CA[i]), aR[i]);
            }
            {
                ull aR[18];
                const ull* r2 = (const ull*)&sm.br2[36];
                #pragma unroll
                for (int i = 0; i < 18; i++) aR[i] = r2[i];
                mm1<36, 72>(sm.wr2 + 36, hA, aR);
                ull* gAo = haU + AOFFU;
                const ull* SA = (const ull*)&sm.redS[36];
                const ull* CA = (const ull*)&sm.redC[36];
                #pragma unroll
                for (int i = 0; i < 18; i++)
                    gAo[i] = fadd2(ffma2(gAo[i], SA[i], CA[i]), aR[i]);
            }
        }
        __syncthreads();
        // pool: 2-stripe partials then final write
        if (t < 144) {
            const int f = t % 72, sI = t / 72;
            const float* pp = (f < 36) ? (sm.out + f) : (sm.h + AOFF + (f - 36));
            const int str = (f < 36) ? OSF : HSF;
            float m = -INFINITY;
            for (int n = sI; n < SN; n += 2) m = fmaxf(m, pp[n * str]);
            sm.redP[t] = m;
        }
        __syncthreads();
        if (t < 72) g_pooled[g * 72 + t] = fmaxf(sm.redP[t], sm.redP[t + 72]);
        __syncthreads();
    }
}

// ---------------------------------------------------------------------------
// MLP (R8/R11/R13 exact, 34.9us measured): TM=8, grid 256, 512 thr, split-k z2.
// ---------------------------------------------------------------------------
struct __align__(16) MSmem {
    ull rowsT[72][5];
    ull z1T[512][5];
    ull z2P[256][5];
    ull z2T[256][5];
};

__global__ void __launch_bounds__(512, 2) mlp_kernel(
    const float* __restrict__ wf1, const float* __restrict__ bf1,
    const float* __restrict__ wf2, const float* __restrict__ bf2,
    const float* __restrict__ wm, const float* __restrict__ bm,
    const float* __restrict__ wl, const float* __restrict__ bl,
    float* __restrict__ out)
{
    extern __shared__ char smraw[];
    MSmem& sm = *reinterpret_cast<MSmem*>(smraw);
    const int tid = threadIdx.x;
    const int r0 = blockIdx.x * 8;

    {
        float* rf = (float*)sm.rowsT;
        for (int i = tid; i < 8 * 72; i += 512) {
            const int k = i / 8, r = i % 8;
            rf[k * 10 + r] = g_pooled[(r0 + r) * 72 + k];
        }
    }
    __syncthreads();

    {
        const int j = tid;
        const float b = __ldg(bf1 + j);
        ull acc[4];
        #pragma unroll
        for (int i = 0; i < 4; i++) acc[i] = pk2(b, b);
        #pragma unroll 8
        for (int k = 0; k < 72; k++) {
            const float w = __ldg(wf1 + k * 512 + j);
            const ull ww = pk2(w, w);
            const ull* rw = sm.rowsT[k];
            #pragma unroll
            for (int i = 0; i < 4; i++) acc[i] = ffma2(ww, rw[i], acc[i]);
        }
        #pragma unroll
        for (int i = 0; i < 4; i++) {
            float2 v = upk2(acc[i]);
            sm.z1T[j][i] = pk2(fmaxf(v.x, 0.f), fmaxf(v.y, 0.f));
        }
    }
    __syncthreads();

    {
        const int jj = tid & 255, half = tid >> 8;
        ull acc[4];
        if (half == 0) {
            const float b = __ldg(bf2 + jj);
            #pragma unroll
            for (int i = 0; i < 4; i++) acc[i] = pk2(b, b);
        } else {
            #pragma unroll
            for (int i = 0; i < 4; i++) acc[i] = 0ull;
        }
        const int k0 = half * 256;
        #pragma unroll 8
        for (int kk = 0; kk < 256; kk++) {
            const int k = k0 + kk;
            const float w = __ldg(wf2 + k * 256 + jj);
            const ull ww = pk2(w, w);
            const ull* zw = sm.z1T[k];
            #pragma unroll
            for (int i = 0; i < 4; i++) acc[i] = ffma2(ww, zw[i], acc[i]);
        }
        if (half == 1) {
            #pragma unroll
            for (int i = 0; i < 4; i++) sm.z2P[jj][i] = acc[i];
        }
        __syncthreads();
        if (half == 0) {
            #pragma unroll
            for (int i = 0; i < 4; i++) {
                float2 v = upk2(fadd2(acc[i], sm.z2P[jj][i]));
                sm.z2T[jj][i] = pk2(fmaxf(v.x, 0.f), fmaxf(v.y, 0.f));
            }
        }
        __syncthreads();
    }

    {
        const int w = tid >> 5, lane = tid & 31;
        if (w < 8) {
            const int rp = w >> 1, hi = w & 1;
            float smv = 0.f, slv = 0.f;
            #pragma unroll 4
            for (int k = lane; k < 256; k += 32) {
                float2 v2 = upk2(sm.z2T[k][rp]);
                const float v = hi ? v2.y : v2.x;
                smv = fmaf(v, __ldg(wm + k), smv);
                slv = fmaf(v, __ldg(wl + k), slv);
            }
            #pragma unroll
            for (int o = 16; o > 0; o >>= 1) {
                smv += __shfl_xor_sync(0xffffffffu, smv, o);
                slv += __shfl_xor_sync(0xffffffffu, slv, o);
            }
            if (lane == 0) {
                out[r0 + w] = smv + __ldg(bm);
                const float ls = tanhf(slv + __ldg(bl));
                out[NG + r0 + w] = LSMIN + 0.5f * (LSMAX - LSMIN) * (ls + 1.0f);
            }
        }
    }
}

// ---------------------------------------------------------------------------
extern "C" void kernel_launch(void* const* d_in, const int* in_sizes, int n_in,
                              void* d_out, int out_size)
{
    const int*   x    = (const int*)d_in[0];
    const float* emb  = (const float*)d_in[2];
    const float* wc1  = (const float*)d_in[3];
    const float* bc1  = (const float*)d_in[4];
    const float* wc2  = (const float*)d_in[5];
    const float* bc2  = (const float*)d_in[6];
    const float* wc3  = (const float*)d_in[7];
    const float* bc3  = (const float*)d_in[8];
    const float* wr1  = (const float*)d_in[9];
    const float* br1  = (const float*)d_in[10];
    const float* wr2  = (const float*)d_in[11];
    const float* br2  = (const float*)d_in[12];
    const float* g1   = (const float*)d_in[13];
    const float* be1  = (const float*)d_in[14];
    const float* a1   = (const float*)d_in[15];
    const float* g2   = (const float*)d_in[16];
    const float* be2  = (const float*)d_in[17];
    const float* a2   = (const float*)d_in[18];
    const float* g3   = (const float*)d_in[19];
    const float* be3  = (const float*)d_in[20];
    const float* a3   = (const float*)d_in[21];
    const float* wf1  = (const float*)d_in[22];
    const float* bf1  = (const float*)d_in[23];
    const float* wf2  = (const float*)d_in[24];
    const float* bf2  = (const float*)d_in[25];
    const float* wm   = (const float*)d_in[26];
    const float* bm   = (const float*)d_in[27];
    const float* wl   = (const float*)d_in[28];
    const float* bl   = (const float*)d_in[29];
    float* out = (float*)d_out;

    cudaFuncSetAttribute(gnn_kernel, cudaFuncAttributeMaxDynamicSharedMemorySize,
                         (int)sizeof(Smem));
    cudaFuncSetAttribute(mlp_kernel, cudaFuncAttributeMaxDynamicSharedMemorySize,
                         (int)sizeof(MSmem));

    gnn_kernel<<<GGRID, NT, sizeof(Smem)>>>(
        x, emb, wc1, bc1, wc2, bc2, wc3, bc3, wr1, br1, wr2, br2,
        g1, be1, a1, g2, be2, a2, g3, be3, a3);

    mlp_kernel<<<NG / 8, 512, sizeof(MSmem)>>>(
        wf1, bf1, wf2, bf2, wm, bm, wl, bl, out);
}